// round 12
// baseline (speedup 1.0000x reference)
#include <cuda_runtime.h>
#include <cuda_bf16.h>
#include <math.h>
#include <stdint.h>

#define HID    2560
#define BATCH  64
#define TSTEPS 500
#define IN_DIM 128
#define GRID   80
#define NSTG   5
#define STAGE_SZ 24576                 // 16KB W (64x256B) + 8KB r (32x256B)
#define WBYTES 16384
#define RBYTES 8192
#define OUT_OFF (NSTG*STAGE_SZ)        // 122880
#define MB_OFF  (OUT_OFF + 8704)       // 131584
#define SMEM_TOTAL (MB_OFF + 128)      // 131712

// static scratch (allocations forbidden)
__device__ __nv_bfloat16 g_Wb[450*8192];            // pre-swizzled W_eff slabs [slab][64h][128k]
__device__ __nv_bfloat16 g_in[TSTEPS*64*IN_DIM];    // pre-swizzled inputs [t][64b][128k]
__device__ __nv_bfloat16 g_rs[4][20*64*128];        // swizzled rates, 4-deep rotation
__device__ int g_flag[40];                          // per-(slab,bh) monotonic write counters

// ---------------------------------------------------------------------------
// Builders. Connectivity (validated at rel_err 1e-8 in fp32 rounds):
//  E col k(<2048): |area(h)-area(k)|<=1, +|w|; I col: same area, -|w|;
//  diagonal removed; input cols only for area-0 rows, +|w_in|.
// 128k slabs per 64h tile: nE {8,12,12,8}, +1 I, (+1 input if area 0)
// → nS {10,13,13,9}; slab bases per area {0,100,230,360}; total 450.
// Swizzle baked into global: 16B chunk ch of row r stored at ch ^ (r&7).
// ---------------------------------------------------------------------------
__global__ void build_W(const float* __restrict__ W_rec, const float* __restrict__ W_in) {
    int idx = blockIdx.x*blockDim.x + threadIdx.x;
    if (idx >= 450*8192) return;
    int blk = idx >> 13, e = idx & 8191;
    int hl = e >> 7, cc = e & 127;
    int a    = (blk<100)?0:(blk<230)?1:(blk<360)?2:3;
    int base = (a==0)?0:(a==1)?100:(a==2)?230:360;
    int nE   = (a==1||a==2)?12:8;
    int nS   = nE + 1 + ((a==0)?1:0);
    int ti = (blk - base)/nS;
    int i  = (blk - base) - ti*nS;
    int hbase = (ti<8) ? a*512 + ti*64 : 2048 + a*128 + (ti-8)*64;
    int h = hbase + hl;
    float v = 0.f;
    if (i < nE) {
        int k = (a>0?a-1:0)*512 + i*128 + cc;
        if (k != h) v = fabsf(W_rec[(size_t)h*HID + k]);
    } else if (i == nE) {
        int k = 2048 + a*128 + cc;
        if (k != h) v = -fabsf(W_rec[(size_t)h*HID + k]);
    } else {
        v = fabsf(W_in[(size_t)h*IN_DIM + cc]);
    }
    int dst = blk*8192 + hl*128 + ((((cc>>3) ^ (hl&7)))<<3) + (cc&7);
    g_Wb[dst] = __float2bfloat16_rn(v);
}

__global__ void build_in(const float* __restrict__ in) {
    int idx = blockIdx.x*blockDim.x + threadIdx.x;
    if (idx >= TSTEPS*64*IN_DIM) return;
    int t = idx >> 13, rem = idx & 8191;
    int b = rem >> 7, k = rem & 127;
    int dst = t*8192 + b*128 + ((((k>>3) ^ (b&7)))<<3) + (k&7);
    g_in[dst] = __float2bfloat16_rn(in[idx]);
}

__global__ void init_k() {
    int idx = blockIdx.x*blockDim.x + threadIdx.x;
    if (idx < 20*64*128) g_rs[0][idx] = __float2bfloat16_rn(0.f);  // r0 = 0
    if (idx < 40) g_flag[idx] = 0;
}

// ---------------------------------------------------------------------------
#define MBAR_INIT(m, c) \
    asm volatile("mbarrier.init.shared.b64 [%0], %1;" :: "r"(m), "r"(c) : "memory")
#define MBAR_EXPECT_TX(m, b) \
    asm volatile("mbarrier.arrive.expect_tx.shared.b64 _, [%0], %1;" :: "r"(m), "r"(b) : "memory")
#define MBAR_ARRIVE(m) \
    asm volatile("mbarrier.arrive.shared.b64 _, [%0];" :: "r"(m) : "memory")
#define BULK_G2S(dst, src, bytes, mbar) \
    asm volatile("cp.async.bulk.shared::cta.global.mbarrier::complete_tx::bytes [%0], [%1], %2, [%3];" \
                 :: "r"(dst), "l"(src), "r"(bytes), "r"(mbar) : "memory")
#define BAR_CONSUMERS() asm volatile("bar.sync 1, 256;" ::: "memory")
__device__ __forceinline__ void mbar_wait(uint32_t mbar, uint32_t parity) {
    uint32_t done;
    asm volatile("{\n\t.reg .pred p;\n\t"
                 "mbarrier.try_wait.parity.acquire.cta.shared::cta.b64 p, [%1], %2;\n\t"
                 "selp.b32 %0, 1, 0, p;\n\t}"
                 : "=r"(done) : "r"(mbar), "r"(parity) : "memory");
    while (!done) {
        asm volatile("{\n\t.reg .pred p;\n\t"
                     "mbarrier.try_wait.parity.acquire.cta.shared::cta.b64 p, [%1], %2, 0x989680;\n\t"
                     "selp.b32 %0, 1, 0, p;\n\t}"
                     : "=r"(done) : "r"(mbar), "r"(parity) : "memory");
    }
}
#define LDSM_X4(r0,r1,r2,r3,addr) \
    asm volatile("ldmatrix.sync.aligned.m8n8.x4.shared.b16 {%0,%1,%2,%3}, [%4];" \
        : "=r"(r0),"=r"(r1),"=r"(r2),"=r"(r3) : "r"(addr))
#define MMA_BF16(c, a0,a1,a2,a3, b0,b1) \
    asm volatile("mma.sync.aligned.m16n8k16.row.col.f32.bf16.bf16.f32 " \
        "{%0,%1,%2,%3},{%4,%5,%6,%7},{%8,%9},{%0,%1,%2,%3};" \
        : "+f"((c)[0]),"+f"((c)[1]),"+f"((c)[2]),"+f"((c)[3]) \
        : "r"(a0),"r"(a1),"r"(a2),"r"(a3),"r"(b0),"r"(b1))

// ---------------------------------------------------------------------------
// Persistent kernel: 80 CTAs x 288 threads. NO global barrier: per-slab flag
// counters order cross-CTA r production/consumption (dataflow pipelining).
// Warp 8 lane 0 = free-running bulk-copy producer; warps 0-7 = LDSM+MMA.
// ---------------------------------------------------------------------------
__global__ void __launch_bounds__(288, 1) rnn_kernel(const float* __restrict__ b_rec,
                                                     float* __restrict__ out) {
    extern __shared__ char sm[];
    uint32_t sb;
    asm("{ .reg .u64 t; cvta.to.shared.u64 t, %1; cvt.u32.u64 %0, t; }" : "=r"(sb) : "l"(sm));
    const uint32_t MB = sb + MB_OFF;   // full[5]@+0, empty[5]@+40
    const int tid = threadIdx.x, wid = tid >> 5, lane = tid & 31;
    const int wm = wid & 3, nh = (wid >> 2) & 1;
    const int g = lane >> 2, cq = lane & 3;
    const int cta = blockIdx.x, tau = cta >> 1, bh = (cta & 1) << 5;
    const int bhIdx = cta & 1;
    const int a = tau/10, ti = tau - 10*a;
    const int hbase = (ti<8) ? a*512 + ti*64 : 2048 + a*128 + (ti-8)*64;
    const int nE    = (a==1||a==2)?12:8;
    const int nS    = nE + 1 + ((a==0)?1:0);
    const int kslab0 = (a>0?(a-1)*4:0);     // first E r-slab
    const int islab  = 16 + a;              // I r-slab
    const int baseA = (a==0)?0:(a==1)?100:(a==2)?230:360;
    const int blkbase = baseA + ti*nS;
    const int slabW  = hbase >> 7;          // slab this tile writes

    if (tid == 0) {
        #pragma unroll
        for (int s = 0; s < NSTG; s++) {
            MBAR_INIT(MB + s*8, 1);        // full: expect_tx arrival + tx bytes
            MBAR_INIT(MB + 40 + s*8, 8);   // empty: 8 consumer-warp arrivals
        }
    }
    __syncthreads();   // all 288 threads, once

    // ===================== producer (warp 8, lane 0) ========================
    if (wid == 8) {
        if (lane == 0) {
            int pf = 0;
            for (int t = 0; t < TSTEPS; t++) {
                const __nv_bfloat16* rin = g_rs[t & 3];
                const __nv_bfloat16* inp = g_in + (size_t)t * 8192;
                const int need = 2*t;
                for (int s = 0; s < nS; s++) {
                    int stg = pf % NSTG;
                    if (pf >= NSTG) mbar_wait(MB + 40 + stg*8, (uint32_t)((pf/NSTG + 1) & 1));
                    MBAR_EXPECT_TX(MB + stg*8, STAGE_SZ);
                    BULK_G2S(sb + stg*STAGE_SZ,
                             g_Wb + (size_t)(blkbase + s)*8192, WBYTES, MB + stg*8);
                    const __nv_bfloat16* rsrc;
                    if (s <= nE) {
                        int k = (s < nE) ? (kslab0 + s) : islab;
                        const int* fp = g_flag + k*2 + bhIdx;
                        int v;
                        do {
                            asm volatile("ld.acquire.gpu.global.b32 %0, [%1];"
                                         : "=r"(v) : "l"(fp));
                        } while (v < need);
                        rsrc = rin + (size_t)k*8192 + bh*128;
                    } else {
                        rsrc = inp + bh*128;
                    }
                    BULK_G2S(sb + stg*STAGE_SZ + WBYTES, rsrc, RBYTES, MB + stg*8);
                    pf++;
                }
            }
        }
        return;   // producer warp (and idle lanes) exits the cooperative region
    }

    // ===================== consumers (warps 0-7) ============================
    const float bias0 = b_rec[hbase + wm*16 + g];
    const float bias1 = b_rec[hbase + wm*16 + 8 + g];

    // ldmatrix lane geometry (chunk-XOR swizzle within 256B rows)
    const int lr = lane & 7, half = (lane >> 3) & 1, kbit = lane >> 4;
    const int rowA = wm*16 + half*8 + lr;
    const int rowB = nh*16 + half*8 + lr;
    const uint32_t aoff = (uint32_t)rowA << 8;
    const uint32_t boff = 16384u + ((uint32_t)rowB << 8);
    const int axor = rowA & 7, bxor = rowB & 7;

    float x0[4], x1[4];
    #pragma unroll
    for (int k = 0; k < 4; k++) { x0[k] = 0.f; x1[k] = 0.f; }

    float* OUT = (float*)(sm + OUT_OFF);   // [32b][68] padded fp32
    int cstg = 0, cph = 0;                 // consumer ring cursor

    for (int t = 0; t < TSTEPS; t++) {
        __nv_bfloat16* __restrict__ rout = g_rs[(t + 1) & 3];

        float acc0[2][4], acc1[2][4];
        #pragma unroll
        for (int p = 0; p < 2; p++)
            #pragma unroll
            for (int k = 0; k < 4; k++) { acc0[p][k] = 0.f; acc1[p][k] = 0.f; }

        for (int s = 0; s < nS; s++) {
            mbar_wait(MB + cstg*8, (uint32_t)cph);
            uint32_t st = sb + (uint32_t)cstg * STAGE_SZ;
            uint32_t pa = st + aoff, pb = st + boff;
            #pragma unroll
            for (int c = 0; c < 8; c++) {
                uint32_t ra0, ra1, ra2, ra3, rb0, rb1, rb2, rb3;
                LDSM_X4(ra0, ra1, ra2, ra3, pa + (uint32_t)(((2*c + kbit) ^ axor) << 4));
                LDSM_X4(rb0, rb1, rb2, rb3, pb + (uint32_t)(((2*c + kbit) ^ bxor) << 4));
                MMA_BF16(acc0[c & 1], ra0, ra1, ra2, ra3, rb0, rb2);
                MMA_BF16(acc1[c & 1], ra0, ra1, ra2, ra3, rb1, rb3);
            }
            if (lane == 0) MBAR_ARRIVE(MB + 40 + cstg*8);
            if (++cstg == NSTG) { cstg = 0; cph ^= 1; }
        }

        // epilogue: x update + retanh into OUT
        {
            int hg = wm*16 + g;
            #pragma unroll
            for (int j = 0; j < 2; j++) {
                float* a0 = j ? acc1[0] : acc0[0];
                float* a1 = j ? acc1[1] : acc0[1];
                float* xx = j ? x1 : x0;
                int b0 = nh*16 + j*8 + 2*cq;
                float xv, r;
                xv = 0.8f*xx[0] + 0.2f*(a0[0] + a1[0] + bias0); xx[0] = xv;
                r = (xv > 0.f) ? tanhf(xv) : 0.f; OUT[(b0  )*68 + hg    ] = r;
                xv = 0.8f*xx[1] + 0.2f*(a0[1] + a1[1] + bias0); xx[1] = xv;
                r = (xv > 0.f) ? tanhf(xv) : 0.f; OUT[(b0+1)*68 + hg    ] = r;
                xv = 0.8f*xx[2] + 0.2f*(a0[2] + a1[2] + bias1); xx[2] = xv;
                r = (xv > 0.f) ? tanhf(xv) : 0.f; OUT[(b0  )*68 + hg + 8] = r;
                xv = 0.8f*xx[3] + 0.2f*(a0[3] + a1[3] + bias1); xx[3] = xv;
                r = (xv > 0.f) ? tanhf(xv) : 0.f; OUT[(b0+1)*68 + hg + 8] = r;
            }
        }
        BAR_CONSUMERS();
        #pragma unroll
        for (int it = 0; it < 2; it++) {
            int f = tid + 256*it;                 // 512 float4s: 32b x 16 h-quads
            int b = f >> 4, hq = f & 15;
            float4 v = *(const float4*)&OUT[b*68 + hq*4];
            *(float4*)&out[(size_t)t*(BATCH*HID) + (size_t)(bh + b)*HID + hbase + hq*4] = v;
            uint32_t p0, p1;
            asm("cvt.rn.bf16x2.f32 %0, %1, %2;" : "=r"(p0) : "f"(v.y), "f"(v.x));
            asm("cvt.rn.bf16x2.f32 %0, %1, %2;" : "=r"(p1) : "f"(v.w), "f"(v.z));
            uint2 pk; pk.x = p0; pk.y = p1;
            int k   = (hbase & 127) + hq*4;
            int ch  = k >> 3;
            int gb  = bh + b;
            int dst = slabW*8192 + gb*128 + ((ch ^ (gb & 7)) << 3) + (k & 7);
            *(uint2*)(rout + dst) = pk;
        }

        // release: writes visible device-wide, then bump our (slab,bh) counter
        __threadfence();
        BAR_CONSUMERS();
        if (tid == 0) atomicAdd(g_flag + slabW*2 + bhIdx, 1);
    }
}

// ---------------------------------------------------------------------------
extern "C" void kernel_launch(void* const* d_in, const int* in_sizes, int n_in,
                              void* d_out, int out_size) {
    const float *inputs = nullptr, *W_rec = nullptr,
                *b_rec = nullptr,  *W_in  = nullptr;
    for (int i = 0; i < n_in; i++) {
        long n = (long)in_sizes[i];
        if      (n == (long)TSTEPS*BATCH*IN_DIM) inputs = (const float*)d_in[i];
        else if (n == (long)HID*HID)             W_rec  = (const float*)d_in[i];
        else if (n == (long)HID)                 b_rec  = (const float*)d_in[i];
        else if (n == (long)HID*IN_DIM)          W_in   = (const float*)d_in[i];
    }
    float* out = (float*)d_out;

    cudaFuncSetAttribute(rnn_kernel, cudaFuncAttributeMaxDynamicSharedMemorySize, SMEM_TOTAL);

    build_W <<<(450*8192 + 255)/256, 256>>>(W_rec, W_in);
    build_in<<<(TSTEPS*64*IN_DIM + 255)/256, 256>>>(inputs);
    init_k  <<<(20*64*128 + 255)/256, 256>>>();
    rnn_kernel<<<GRID, 288, SMEM_TOTAL>>>(b_rec, out);
}

// round 13
// speedup vs baseline: 1.0704x; 1.0704x over previous
#include <cuda_runtime.h>
#include <cuda_bf16.h>
#include <math.h>
#include <stdint.h>

#define HID    2560
#define BATCH  64
#define TSTEPS 500
#define IN_DIM 128
#define GRID   80
#define NSTG   6
#define STAGE_SZ 24576                 // 16KB W (64x256B) + 8KB r (32x256B)
#define WBYTES 16384
#define RBYTES 8192
#define OUT_OFF (NSTG*STAGE_SZ)        // 147456
#define MB_OFF  (OUT_OFF + 8704)       // 156160
#define SMEM_TOTAL (MB_OFF + 128)      // 156288

// static scratch (allocations forbidden)
__device__ __nv_bfloat16 g_Wb[450*8192];            // pre-swizzled W_eff slabs [slab][64h][128k]
__device__ __nv_bfloat16 g_in[TSTEPS*64*IN_DIM];    // pre-swizzled inputs [t][64b][128k]
__device__ __nv_bfloat16 g_rs[4][20*64*128];        // swizzled rates, 4-deep rotation
__device__ int g_flag[40];                          // per-(slab,bh) monotonic write counters

// ---------------------------------------------------------------------------
// Builders. Connectivity (validated at rel_err 1e-8 in fp32 rounds):
//  E col k(<2048): |area(h)-area(k)|<=1, +|w|; I col: same area, -|w|;
//  diagonal removed; input cols only for area-0 rows, +|w_in|.
// 128k slabs per 64h tile: nE {8,12,12,8}, +1 I, (+1 input if area 0)
// → nS {10,13,13,9}; slab bases per area {0,100,230,360}; total 450.
// Swizzle baked into global: 16B chunk ch of row r stored at ch ^ (r&7).
// ---------------------------------------------------------------------------
__global__ void build_W(const float* __restrict__ W_rec, const float* __restrict__ W_in) {
    int idx = blockIdx.x*blockDim.x + threadIdx.x;
    if (idx >= 450*8192) return;
    int blk = idx >> 13, e = idx & 8191;
    int hl = e >> 7, cc = e & 127;
    int a    = (blk<100)?0:(blk<230)?1:(blk<360)?2:3;
    int base = (a==0)?0:(a==1)?100:(a==2)?230:360;
    int nE   = (a==1||a==2)?12:8;
    int nS   = nE + 1 + ((a==0)?1:0);
    int ti = (blk - base)/nS;
    int i  = (blk - base) - ti*nS;
    int hbase = (ti<8) ? a*512 + ti*64 : 2048 + a*128 + (ti-8)*64;
    int h = hbase + hl;
    float v = 0.f;
    if (i < nE) {
        int k = (a>0?a-1:0)*512 + i*128 + cc;
        if (k != h) v = fabsf(W_rec[(size_t)h*HID + k]);
    } else if (i == nE) {
        int k = 2048 + a*128 + cc;
        if (k != h) v = -fabsf(W_rec[(size_t)h*HID + k]);
    } else {
        v = fabsf(W_in[(size_t)h*IN_DIM + cc]);
    }
    int dst = blk*8192 + hl*128 + ((((cc>>3) ^ (hl&7)))<<3) + (cc&7);
    g_Wb[dst] = __float2bfloat16_rn(v);
}

__global__ void build_in(const float* __restrict__ in) {
    int idx = blockIdx.x*blockDim.x + threadIdx.x;
    if (idx >= TSTEPS*64*IN_DIM) return;
    int t = idx >> 13, rem = idx & 8191;
    int b = rem >> 7, k = rem & 127;
    int dst = t*8192 + b*128 + ((((k>>3) ^ (b&7)))<<3) + (k&7);
    g_in[dst] = __float2bfloat16_rn(in[idx]);
}

__global__ void init_k() {
    int idx = blockIdx.x*blockDim.x + threadIdx.x;
    if (idx < 20*64*128) g_rs[0][idx] = __float2bfloat16_rn(0.f);  // r0 = 0
    if (idx < 40) g_flag[idx] = 0;
}

// ---------------------------------------------------------------------------
#define MBAR_INIT(m, c) \
    asm volatile("mbarrier.init.shared.b64 [%0], %1;" :: "r"(m), "r"(c) : "memory")
#define MBAR_EXPECT_TX(m, b) \
    asm volatile("mbarrier.arrive.expect_tx.shared.b64 _, [%0], %1;" :: "r"(m), "r"(b) : "memory")
#define MBAR_ARRIVE(m) \
    asm volatile("mbarrier.arrive.shared.b64 _, [%0];" :: "r"(m) : "memory")
#define BULK_G2S(dst, src, bytes, mbar) \
    asm volatile("cp.async.bulk.shared::cta.global.mbarrier::complete_tx::bytes [%0], [%1], %2, [%3];" \
                 :: "r"(dst), "l"(src), "r"(bytes), "r"(mbar) : "memory")
#define BAR_CONSUMERS() asm volatile("bar.sync 1, 256;" ::: "memory")
__device__ __forceinline__ void mbar_wait(uint32_t mbar, uint32_t parity) {
    uint32_t done;
    asm volatile("{\n\t.reg .pred p;\n\t"
                 "mbarrier.try_wait.parity.acquire.cta.shared::cta.b64 p, [%1], %2;\n\t"
                 "selp.b32 %0, 1, 0, p;\n\t}"
                 : "=r"(done) : "r"(mbar), "r"(parity) : "memory");
    while (!done) {
        asm volatile("{\n\t.reg .pred p;\n\t"
                     "mbarrier.try_wait.parity.acquire.cta.shared::cta.b64 p, [%1], %2, 0x989680;\n\t"
                     "selp.b32 %0, 1, 0, p;\n\t}"
                     : "=r"(done) : "r"(mbar), "r"(parity) : "memory");
    }
}
#define LDSM_X4(r0,r1,r2,r3,addr) \
    asm volatile("ldmatrix.sync.aligned.m8n8.x4.shared.b16 {%0,%1,%2,%3}, [%4];" \
        : "=r"(r0),"=r"(r1),"=r"(r2),"=r"(r3) : "r"(addr))
#define MMA_BF16(c, a0,a1,a2,a3, b0,b1) \
    asm volatile("mma.sync.aligned.m16n8k16.row.col.f32.bf16.bf16.f32 " \
        "{%0,%1,%2,%3},{%4,%5,%6,%7},{%8,%9},{%0,%1,%2,%3};" \
        : "+f"((c)[0]),"+f"((c)[1]),"+f"((c)[2]),"+f"((c)[3]) \
        : "r"(a0),"r"(a1),"r"(a2),"r"(a3),"r"(b0),"r"(b1))
__device__ __forceinline__ float retanh_fast(float x) {
    float m = fmaxf(x, 0.f), r;
    asm("tanh.approx.f32 %0, %1;" : "=f"(r) : "f"(m));
    return r;
}

// ---------------------------------------------------------------------------
// Persistent kernel: 80 CTAs x 288 threads. Dataflow sync via per-slab flag
// counters; warp 8 lane 0 = bulk-copy producer; warps 0-7 = LDSM+MMA.
// Epilogue releases the recurrence flag BEFORE streaming the fp32 out tile.
// ---------------------------------------------------------------------------
__global__ void __launch_bounds__(288, 1) rnn_kernel(const float* __restrict__ b_rec,
                                                     float* __restrict__ out) {
    extern __shared__ char sm[];
    uint32_t sb;
    asm("{ .reg .u64 t; cvta.to.shared.u64 t, %1; cvt.u32.u64 %0, t; }" : "=r"(sb) : "l"(sm));
    const uint32_t MB = sb + MB_OFF;   // full[6]@+0, empty[6]@+48
    const int tid = threadIdx.x, wid = tid >> 5, lane = tid & 31;
    const int wm = wid & 3, nh = (wid >> 2) & 1;
    const int g = lane >> 2, cq = lane & 3;
    const int cta = blockIdx.x, tau = cta >> 1, bh = (cta & 1) << 5;
    const int bhIdx = cta & 1;
    const int a = tau/10, ti = tau - 10*a;
    const int hbase = (ti<8) ? a*512 + ti*64 : 2048 + a*128 + (ti-8)*64;
    const int nE    = (a==1||a==2)?12:8;
    const int nS    = nE + 1 + ((a==0)?1:0);
    const int kslab0 = (a>0?(a-1)*4:0);     // first E r-slab
    const int islab  = 16 + a;              // I r-slab
    const int baseA = (a==0)?0:(a==1)?100:(a==2)?230:360;
    const int blkbase = baseA + ti*nS;
    const int slabW  = hbase >> 7;          // slab this tile writes

    if (tid == 0) {
        #pragma unroll
        for (int s = 0; s < NSTG; s++) {
            MBAR_INIT(MB + s*8, 1);          // full: expect_tx arrival + tx bytes
            MBAR_INIT(MB + 48 + s*8, 8);     // empty: 8 consumer-warp arrivals
        }
    }
    __syncthreads();   // all 288 threads, once

    // ===================== producer (warp 8, lane 0) ========================
    if (wid == 8) {
        if (lane == 0) {
            int pf = 0;
            for (int t = 0; t < TSTEPS; t++) {
                const __nv_bfloat16* rin = g_rs[t & 3];
                const __nv_bfloat16* inp = g_in + (size_t)t * 8192;
                const int need = 2*t;
                for (int s = 0; s < nS; s++) {
                    int stg = pf % NSTG;
                    if (pf >= NSTG) mbar_wait(MB + 48 + stg*8, (uint32_t)((pf/NSTG + 1) & 1));
                    MBAR_EXPECT_TX(MB + stg*8, STAGE_SZ);
                    BULK_G2S(sb + stg*STAGE_SZ,
                             g_Wb + (size_t)(blkbase + s)*8192, WBYTES, MB + stg*8);
                    const __nv_bfloat16* rsrc;
                    if (s <= nE) {
                        int k = (s < nE) ? (kslab0 + s) : islab;
                        const int* fp = g_flag + k*2 + bhIdx;
                        int v;
                        do {
                            asm volatile("ld.acquire.gpu.global.b32 %0, [%1];"
                                         : "=r"(v) : "l"(fp));
                        } while (v < need);
                        rsrc = rin + (size_t)k*8192 + bh*128;
                    } else {
                        rsrc = inp + bh*128;
                    }
                    BULK_G2S(sb + stg*STAGE_SZ + WBYTES, rsrc, RBYTES, MB + stg*8);
                    pf++;
                }
            }
        }
        return;
    }

    // ===================== consumers (warps 0-7) ============================
    const float bias0 = b_rec[hbase + wm*16 + g];
    const float bias1 = b_rec[hbase + wm*16 + 8 + g];

    // ldmatrix lane geometry (chunk-XOR swizzle within 256B rows)
    const int lr = lane & 7, half = (lane >> 3) & 1, kbit = lane >> 4;
    const int rowA = wm*16 + half*8 + lr;
    const int rowB = nh*16 + half*8 + lr;
    const uint32_t aoff = (uint32_t)rowA << 8;
    const uint32_t boff = 16384u + ((uint32_t)rowB << 8);
    const int axor = rowA & 7, bxor = rowB & 7;

    float x0[4], x1[4];
    #pragma unroll
    for (int k = 0; k < 4; k++) { x0[k] = 0.f; x1[k] = 0.f; }

    float* OUT = (float*)(sm + OUT_OFF);   // [32b][68] padded fp32
    int cstg = 0, cph = 0;                 // consumer ring cursor

    for (int t = 0; t < TSTEPS; t++) {
        __nv_bfloat16* __restrict__ rout = g_rs[(t + 1) & 3];

        float acc0[2][4], acc1[2][4];
        #pragma unroll
        for (int p = 0; p < 2; p++)
            #pragma unroll
            for (int k = 0; k < 4; k++) { acc0[p][k] = 0.f; acc1[p][k] = 0.f; }

        for (int s = 0; s < nS; s++) {
            mbar_wait(MB + cstg*8, (uint32_t)cph);
            uint32_t st = sb + (uint32_t)cstg * STAGE_SZ;
            uint32_t pa = st + aoff, pb = st + boff;
            #pragma unroll
            for (int c = 0; c < 8; c++) {
                uint32_t ra0, ra1, ra2, ra3, rb0, rb1, rb2, rb3;
                LDSM_X4(ra0, ra1, ra2, ra3, pa + (uint32_t)(((2*c + kbit) ^ axor) << 4));
                LDSM_X4(rb0, rb1, rb2, rb3, pb + (uint32_t)(((2*c + kbit) ^ bxor) << 4));
                MMA_BF16(acc0[c & 1], ra0, ra1, ra2, ra3, rb0, rb2);
                MMA_BF16(acc1[c & 1], ra0, ra1, ra2, ra3, rb1, rb3);
            }
            if (lane == 0) MBAR_ARRIVE(MB + 48 + cstg*8);
            if (++cstg == NSTG) { cstg = 0; cph ^= 1; }
        }

        // epilogue pass 0: x update + fast retanh into OUT (critical path)
        {
            int hg = wm*16 + g;
            #pragma unroll
            for (int j = 0; j < 2; j++) {
                float* a0 = j ? acc1[0] : acc0[0];
                float* a1 = j ? acc1[1] : acc0[1];
                float* xx = j ? x1 : x0;
                int b0 = nh*16 + j*8 + 2*cq;
                float xv;
                xv = 0.8f*xx[0] + 0.2f*(a0[0] + a1[0] + bias0); xx[0] = xv;
                OUT[(b0  )*68 + hg    ] = retanh_fast(xv);
                xv = 0.8f*xx[1] + 0.2f*(a0[1] + a1[1] + bias0); xx[1] = xv;
                OUT[(b0+1)*68 + hg    ] = retanh_fast(xv);
                xv = 0.8f*xx[2] + 0.2f*(a0[2] + a1[2] + bias1); xx[2] = xv;
                OUT[(b0  )*68 + hg + 8] = retanh_fast(xv);
                xv = 0.8f*xx[3] + 0.2f*(a0[3] + a1[3] + bias1); xx[3] = xv;
                OUT[(b0+1)*68 + hg + 8] = retanh_fast(xv);
            }
        }
        BAR_CONSUMERS();

        // epilogue pass 1: recurrence-critical bf16 rout writes, fence, flag
        float4 v0, v1;
        {
            int f0 = tid, f1 = tid + 256;
            int b0 = f0 >> 4, hq0 = f0 & 15;
            int b1 = f1 >> 4, hq1 = f1 & 15;
            v0 = *(const float4*)&OUT[b0*68 + hq0*4];
            v1 = *(const float4*)&OUT[b1*68 + hq1*4];
            uint32_t p0, p1;
            uint2 pk;
            int k0 = (hbase & 127) + hq0*4, ch0 = k0 >> 3, gb0 = bh + b0;
            asm("cvt.rn.bf16x2.f32 %0, %1, %2;" : "=r"(p0) : "f"(v0.y), "f"(v0.x));
            asm("cvt.rn.bf16x2.f32 %0, %1, %2;" : "=r"(p1) : "f"(v0.w), "f"(v0.z));
            pk.x = p0; pk.y = p1;
            *(uint2*)(rout + slabW*8192 + gb0*128 + ((ch0 ^ (gb0 & 7)) << 3) + (k0 & 7)) = pk;
            int k1 = (hbase & 127) + hq1*4, ch1 = k1 >> 3, gb1 = bh + b1;
            asm("cvt.rn.bf16x2.f32 %0, %1, %2;" : "=r"(p0) : "f"(v1.y), "f"(v1.x));
            asm("cvt.rn.bf16x2.f32 %0, %1, %2;" : "=r"(p1) : "f"(v1.w), "f"(v1.z));
            pk.x = p0; pk.y = p1;
            *(uint2*)(rout + slabW*8192 + gb1*128 + ((ch1 ^ (gb1 & 7)) << 3) + (k1 & 7)) = pk;
        }
        __threadfence();
        BAR_CONSUMERS();
        if (tid == 0) atomicAdd(g_flag + slabW*2 + bhIdx, 1);

        // epilogue pass 2: fp32 out tile (off the recurrence critical path)
        {
            int f0 = tid, f1 = tid + 256;
            int b0 = f0 >> 4, hq0 = f0 & 15;
            int b1 = f1 >> 4, hq1 = f1 & 15;
            float* obase = out + (size_t)t*(BATCH*HID) + hbase;
            *(float4*)&obase[(size_t)(bh + b0)*HID + hq0*4] = v0;
            *(float4*)&obase[(size_t)(bh + b1)*HID + hq1*4] = v1;
        }
    }
}

// ---------------------------------------------------------------------------
extern "C" void kernel_launch(void* const* d_in, const int* in_sizes, int n_in,
                              void* d_out, int out_size) {
    const float *inputs = nullptr, *W_rec = nullptr,
                *b_rec = nullptr,  *W_in  = nullptr;
    for (int i = 0; i < n_in; i++) {
        long n = (long)in_sizes[i];
        if      (n == (long)TSTEPS*BATCH*IN_DIM) inputs = (const float*)d_in[i];
        else if (n == (long)HID*HID)             W_rec  = (const float*)d_in[i];
        else if (n == (long)HID)                 b_rec  = (const float*)d_in[i];
        else if (n == (long)HID*IN_DIM)          W_in   = (const float*)d_in[i];
    }
    float* out = (float*)d_out;

    cudaFuncSetAttribute(rnn_kernel, cudaFuncAttributeMaxDynamicSharedMemorySize, SMEM_TOTAL);

    build_W <<<(450*8192 + 255)/256, 256>>>(W_rec, W_in);
    build_in<<<(TSTEPS*64*IN_DIM + 255)/256, 256>>>(inputs);
    init_k  <<<(20*64*128 + 255)/256, 256>>>();
    rnn_kernel<<<GRID, 288, SMEM_TOTAL>>>(b_rec, out);
}

// round 14
// speedup vs baseline: 1.2435x; 1.1618x over previous
#include <cuda_runtime.h>
#include <cuda_bf16.h>
#include <math.h>
#include <stdint.h>

#define HID    2560
#define BATCH  64
#define TSTEPS 500
#define IN_DIM 128
#define GRID   80
#define NSTG   3
#define STAGE_SZ 49152                 // pair group: 32KB W + 16KB r
#define OUT_OFF (NSTG*STAGE_SZ)        // 147456
#define MB_OFF  (OUT_OFF + 8704)       // 156160
#define SMEM_TOTAL (MB_OFF + 128)      // 156288

// static scratch (allocations forbidden)
__device__ __nv_bfloat16 g_Wb[450*8192];            // pre-swizzled W_eff slabs [slab][64h][128k]
__device__ __nv_bfloat16 g_in[TSTEPS*64*IN_DIM];    // pre-swizzled inputs [t][64b][128k]
__device__ __nv_bfloat16 g_rs[4][2*20*4096];        // swizzled rates [buf][bh][slab][32b][128k]
__device__ int g_flag[40];                          // per-(slab,bh) monotonic write counters

// ---------------------------------------------------------------------------
// Builders. Connectivity (validated at rel_err 1e-8 in fp32 rounds):
//  E col k(<2048): |area(h)-area(k)|<=1, +|w|; I col: same area, -|w|;
//  diagonal removed; input cols only for area-0 rows, +|w_in|.
// 128k slabs per 64h tile: nE {8,12,12,8}, +1 I, (+1 input if area 0)
// → nS {10,13,13,9}; slab bases per area {0,100,230,360}; total 450.
// Swizzle baked into global: 16B chunk ch of row r stored at ch ^ (r&7).
// ---------------------------------------------------------------------------
__global__ void build_W(const float* __restrict__ W_rec, const float* __restrict__ W_in) {
    int idx = blockIdx.x*blockDim.x + threadIdx.x;
    if (idx >= 450*8192) return;
    int blk = idx >> 13, e = idx & 8191;
    int hl = e >> 7, cc = e & 127;
    int a    = (blk<100)?0:(blk<230)?1:(blk<360)?2:3;
    int base = (a==0)?0:(a==1)?100:(a==2)?230:360;
    int nE   = (a==1||a==2)?12:8;
    int nS   = nE + 1 + ((a==0)?1:0);
    int ti = (blk - base)/nS;
    int i  = (blk - base) - ti*nS;
    int hbase = (ti<8) ? a*512 + ti*64 : 2048 + a*128 + (ti-8)*64;
    int h = hbase + hl;
    float v = 0.f;
    if (i < nE) {
        int k = (a>0?a-1:0)*512 + i*128 + cc;
        if (k != h) v = fabsf(W_rec[(size_t)h*HID + k]);
    } else if (i == nE) {
        int k = 2048 + a*128 + cc;
        if (k != h) v = -fabsf(W_rec[(size_t)h*HID + k]);
    } else {
        v = fabsf(W_in[(size_t)h*IN_DIM + cc]);
    }
    int dst = blk*8192 + hl*128 + ((((cc>>3) ^ (hl&7)))<<3) + (cc&7);
    g_Wb[dst] = __float2bfloat16_rn(v);
}

__global__ void build_in(const float* __restrict__ in) {
    int idx = blockIdx.x*blockDim.x + threadIdx.x;
    if (idx >= TSTEPS*64*IN_DIM) return;
    int t = idx >> 13, rem = idx & 8191;
    int b = rem >> 7, k = rem & 127;
    int dst = t*8192 + b*128 + ((((k>>3) ^ (b&7)))<<3) + (k&7);
    g_in[dst] = __float2bfloat16_rn(in[idx]);
}

__global__ void init_k() {
    int idx = blockIdx.x*blockDim.x + threadIdx.x;
    if (idx < 2*20*4096) g_rs[0][idx] = __float2bfloat16_rn(0.f);  // r0 = 0
    if (idx < 40) g_flag[idx] = 0;
}

// ---------------------------------------------------------------------------
#define MBAR_INIT(m, c) \
    asm volatile("mbarrier.init.shared.b64 [%0], %1;" :: "r"(m), "r"(c) : "memory")
#define MBAR_EXPECT_TX(m, b) \
    asm volatile("mbarrier.arrive.expect_tx.shared.b64 _, [%0], %1;" :: "r"(m), "r"(b) : "memory")
#define MBAR_ARRIVE(m) \
    asm volatile("mbarrier.arrive.shared.b64 _, [%0];" :: "r"(m) : "memory")
#define BULK_G2S(dst, src, bytes, mbar) \
    asm volatile("cp.async.bulk.shared::cta.global.mbarrier::complete_tx::bytes [%0], [%1], %2, [%3];" \
                 :: "r"(dst), "l"(src), "r"(bytes), "r"(mbar) : "memory")
#define BAR_CONSUMERS() asm volatile("bar.sync 1, 256;" ::: "memory")
__device__ __forceinline__ void mbar_wait(uint32_t mbar, uint32_t parity) {
    uint32_t done;
    asm volatile("{\n\t.reg .pred p;\n\t"
                 "mbarrier.try_wait.parity.acquire.cta.shared::cta.b64 p, [%1], %2;\n\t"
                 "selp.b32 %0, 1, 0, p;\n\t}"
                 : "=r"(done) : "r"(mbar), "r"(parity) : "memory");
    while (!done) {
        asm volatile("{\n\t.reg .pred p;\n\t"
                     "mbarrier.try_wait.parity.acquire.cta.shared::cta.b64 p, [%1], %2, 0x989680;\n\t"
                     "selp.b32 %0, 1, 0, p;\n\t}"
                     : "=r"(done) : "r"(mbar), "r"(parity) : "memory");
    }
}
#define LDSM_X4(r0,r1,r2,r3,addr) \
    asm volatile("ldmatrix.sync.aligned.m8n8.x4.shared.b16 {%0,%1,%2,%3}, [%4];" \
        : "=r"(r0),"=r"(r1),"=r"(r2),"=r"(r3) : "r"(addr))
#define MMA_BF16(c, a0,a1,a2,a3, b0,b1) \
    asm volatile("mma.sync.aligned.m16n8k16.row.col.f32.bf16.bf16.f32 " \
        "{%0,%1,%2,%3},{%4,%5,%6,%7},{%8,%9},{%0,%1,%2,%3};" \
        : "+f"((c)[0]),"+f"((c)[1]),"+f"((c)[2]),"+f"((c)[3]) \
        : "r"(a0),"r"(a1),"r"(a2),"r"(a3),"r"(b0),"r"(b1))
__device__ __forceinline__ float retanh_fast(float x) {
    float m = fmaxf(x, 0.f), r;
    asm("tanh.approx.f32 %0, %1;" : "=f"(r) : "f"(m));
    return r;
}

// ---------------------------------------------------------------------------
// Persistent kernel: 80 CTAs x 288 threads. Dataflow sync via per-slab flags.
// Paired-slab stages (48KB, ring of 3); warp 8 lane 0 = bulk producer;
// warps 0-7 = LDSM+MMA with 4 accumulator chains per n-block.
// ---------------------------------------------------------------------------
__global__ void __launch_bounds__(288, 1) rnn_kernel(const float* __restrict__ b_rec,
                                                     float* __restrict__ out) {
    extern __shared__ char sm[];
    uint32_t sb;
    asm("{ .reg .u64 t; cvta.to.shared.u64 t, %1; cvt.u32.u64 %0, t; }" : "=r"(sb) : "l"(sm));
    const uint32_t MB = sb + MB_OFF;   // full[3]@+0, empty[3]@+24
    const int tid = threadIdx.x, wid = tid >> 5, lane = tid & 31;
    const int wm = wid & 3, nh = (wid >> 2) & 1;
    const int g = lane >> 2, cq = lane & 3;
    const int cta = blockIdx.x, tau = cta >> 1, bh = (cta & 1) << 5;
    const int bhIdx = cta & 1;
    const int a = tau/10, ti = tau - 10*a;
    const int hbase = (ti<8) ? a*512 + ti*64 : 2048 + a*128 + (ti-8)*64;
    const int nE    = (a==1||a==2)?12:8;
    const int nGE   = nE >> 1;              // E pair-groups
    const int kslab0 = (a>0?(a-1)*4:0);     // first E r-slab
    const int islab  = 16 + a;              // I r-slab
    const int baseA = (a==0)?0:(a==1)?100:(a==2)?230:360;
    const int nS    = nE + 1 + ((a==0)?1:0);
    const int blkbase = baseA + ti*nS;
    const int slabW  = hbase >> 7;          // slab this tile writes
    const int tailN  = (a==0) ? 2 : 1;      // slabs in tail group

    if (tid == 0) {
        #pragma unroll
        for (int s = 0; s < NSTG; s++) {
            MBAR_INIT(MB + s*8, 1);          // full: expect_tx + tx bytes
            MBAR_INIT(MB + 24 + s*8, 8);     // empty: 8 consumer-warp arrivals
        }
    }
    __syncthreads();   // all 288 threads, once

    // ===================== producer (warp 8, lane 0) ========================
    if (wid == 8) {
        if (lane == 0) {
            int pf = 0;
            const int nG = nGE + 1;
            for (int t = 0; t < TSTEPS; t++) {
                const __nv_bfloat16* rin = g_rs[t & 3] + (size_t)bhIdx*81920;
                const __nv_bfloat16* inp = g_in + (size_t)t*8192 + bh*128;
                const int need = 2*t;
                for (int gi = 0; gi < nG; gi++) {
                    int stg = pf % NSTG;
                    if (pf >= NSTG) mbar_wait(MB + 24 + stg*8, (uint32_t)((pf/NSTG + 1) & 1));
                    uint32_t st = sb + (uint32_t)stg * STAGE_SZ;
                    if (gi < nGE) {
                        MBAR_EXPECT_TX(MB + stg*8, 49152u);
                        BULK_G2S(st, g_Wb + (size_t)(blkbase + 2*gi)*8192, 32768u, MB + stg*8);
                        int k0s = kslab0 + 2*gi;
                        const int* fp0 = g_flag + k0s*2 + bhIdx;
                        const int* fp1 = g_flag + (k0s+1)*2 + bhIdx;
                        int v;
                        do { asm volatile("ld.acquire.gpu.global.b32 %0, [%1];" : "=r"(v) : "l"(fp0)); } while (v < need);
                        do { asm volatile("ld.acquire.gpu.global.b32 %0, [%1];" : "=r"(v) : "l"(fp1)); } while (v < need);
                        BULK_G2S(st + 32768u, rin + (size_t)k0s*4096, 16384u, MB + stg*8);
                    } else if (a == 0) {
                        MBAR_EXPECT_TX(MB + stg*8, 49152u);
                        BULK_G2S(st, g_Wb + (size_t)(blkbase + nE)*8192, 32768u, MB + stg*8);
                        const int* fp = g_flag + islab*2 + bhIdx;
                        int v;
                        do { asm volatile("ld.acquire.gpu.global.b32 %0, [%1];" : "=r"(v) : "l"(fp)); } while (v < need);
                        BULK_G2S(st + 32768u, rin + (size_t)islab*4096, 8192u, MB + stg*8);
                        BULK_G2S(st + 40960u, inp, 8192u, MB + stg*8);
                    } else {
                        MBAR_EXPECT_TX(MB + stg*8, 24576u);
                        BULK_G2S(st, g_Wb + (size_t)(blkbase + nE)*8192, 16384u, MB + stg*8);
                        const int* fp = g_flag + islab*2 + bhIdx;
                        int v;
                        do { asm volatile("ld.acquire.gpu.global.b32 %0, [%1];" : "=r"(v) : "l"(fp)); } while (v < need);
                        BULK_G2S(st + 32768u, rin + (size_t)islab*4096, 8192u, MB + stg*8);
                    }
                    pf++;
                }
            }
        }
        return;
    }

    // ===================== consumers (warps 0-7) ============================
    const float bias0 = b_rec[hbase + wm*16 + g];
    const float bias1 = b_rec[hbase + wm*16 + 8 + g];

    // ldmatrix lane geometry (chunk-XOR swizzle within 256B rows)
    const int lr = lane & 7, half = (lane >> 3) & 1, kbit = lane >> 4;
    const int rowA = wm*16 + half*8 + lr;
    const int rowB = nh*16 + half*8 + lr;
    const uint32_t aoff = (uint32_t)rowA << 8;
    const uint32_t boff = 32768u + ((uint32_t)rowB << 8);
    const int axor = rowA & 7, bxor = rowB & 7;

    float x0[4], x1[4];
    #pragma unroll
    for (int k = 0; k < 4; k++) { x0[k] = 0.f; x1[k] = 0.f; }

    float* OUT = (float*)(sm + OUT_OFF);   // [32b][68] padded fp32
    int cstg = 0, cph = 0;                 // consumer ring cursor

    for (int t = 0; t < TSTEPS; t++) {
        __nv_bfloat16* __restrict__ rout = g_rs[(t + 1) & 3] + (size_t)bhIdx*81920;

        float accA[4][4], accB[4][4];      // 4 chains per n-block
        #pragma unroll
        for (int p = 0; p < 4; p++)
            #pragma unroll
            for (int k = 0; k < 4; k++) { accA[p][k] = 0.f; accB[p][k] = 0.f; }

        // E pair-groups: 16 MMA-iterations per stage
        for (int gi = 0; gi < nGE; gi++) {
            mbar_wait(MB + cstg*8, (uint32_t)cph);
            uint32_t st = sb + (uint32_t)cstg * STAGE_SZ;
            #pragma unroll
            for (int c2 = 0; c2 < 16; c2++) {
                int j = c2 >> 3, c = c2 & 7, chn = c2 & 3;
                uint32_t pa = st + (uint32_t)(j*16384) + aoff;
                uint32_t pb = st + (uint32_t)(j*8192) + boff;
                uint32_t ra0, ra1, ra2, ra3, rb0, rb1, rb2, rb3;
                LDSM_X4(ra0, ra1, ra2, ra3, pa + (uint32_t)(((2*c + kbit) ^ axor) << 4));
                LDSM_X4(rb0, rb1, rb2, rb3, pb + (uint32_t)(((2*c + kbit) ^ bxor) << 4));
                MMA_BF16(accA[chn], ra0, ra1, ra2, ra3, rb0, rb2);
                MMA_BF16(accB[chn], ra0, ra1, ra2, ra3, rb1, rb3);
            }
            if (lane == 0) MBAR_ARRIVE(MB + 24 + cstg*8);
            if (++cstg == NSTG) { cstg = 0; cph ^= 1; }
        }
        // tail group (I, + input for area 0)
        {
            mbar_wait(MB + cstg*8, (uint32_t)cph);
            uint32_t st = sb + (uint32_t)cstg * STAGE_SZ;
            for (int j = 0; j < tailN; j++) {
                uint32_t pa = st + (uint32_t)(j*16384) + aoff;
                uint32_t pb = st + (uint32_t)(j*8192) + boff;
                #pragma unroll
                for (int c = 0; c < 8; c++) {
                    int chn = c & 3;
                    uint32_t ra0, ra1, ra2, ra3, rb0, rb1, rb2, rb3;
                    LDSM_X4(ra0, ra1, ra2, ra3, pa + (uint32_t)(((2*c + kbit) ^ axor) << 4));
                    LDSM_X4(rb0, rb1, rb2, rb3, pb + (uint32_t)(((2*c + kbit) ^ bxor) << 4));
                    MMA_BF16(accA[chn], ra0, ra1, ra2, ra3, rb0, rb2);
                    MMA_BF16(accB[chn], ra0, ra1, ra2, ra3, rb1, rb3);
                }
            }
            if (lane == 0) MBAR_ARRIVE(MB + 24 + cstg*8);
            if (++cstg == NSTG) { cstg = 0; cph ^= 1; }
        }

        // epilogue pass 0: x update + fast retanh into OUT
        {
            int hg = wm*16 + g;
            #pragma unroll
            for (int j = 0; j < 2; j++) {
                float (*ac)[4] = j ? accB : accA;
                float* xx = j ? x1 : x0;
                int b0 = nh*16 + j*8 + 2*cq;
                #pragma unroll
                for (int e = 0; e < 4; e++) {
                    float s = (ac[0][e] + ac[1][e]) + (ac[2][e] + ac[3][e]);
                    float bias = (e < 2) ? bias0 : bias1;
                    float xv = 0.8f*xx[e] + 0.2f*(s + bias);
                    xx[e] = xv;
                    int bb = b0 + (e & 1);
                    int hh = hg + ((e >> 1) << 3);
                    OUT[bb*68 + hh] = retanh_fast(xv);
                }
            }
        }
        BAR_CONSUMERS();

        // epilogue pass 1: recurrence-critical bf16 rout writes, fence, flag
        float4 v0, v1;
        {
            int f0 = tid, f1 = tid + 256;
            int b0 = f0 >> 4, hq0 = f0 & 15;
            int b1 = f1 >> 4, hq1 = f1 & 15;
            v0 = *(const float4*)&OUT[b0*68 + hq0*4];
            v1 = *(const float4*)&OUT[b1*68 + hq1*4];
            uint32_t p0, p1;
            uint2 pk;
            int k0 = (hbase & 127) + hq0*4, ch0 = k0 >> 3;
            asm("cvt.rn.bf16x2.f32 %0, %1, %2;" : "=r"(p0) : "f"(v0.y), "f"(v0.x));
            asm("cvt.rn.bf16x2.f32 %0, %1, %2;" : "=r"(p1) : "f"(v0.w), "f"(v0.z));
            pk.x = p0; pk.y = p1;
            *(uint2*)(rout + (size_t)slabW*4096 + b0*128 + ((ch0 ^ (b0 & 7)) << 3) + (k0 & 7)) = pk;
            int k1 = (hbase & 127) + hq1*4, ch1 = k1 >> 3;
            asm("cvt.rn.bf16x2.f32 %0, %1, %2;" : "=r"(p0) : "f"(v1.y), "f"(v1.x));
            asm("cvt.rn.bf16x2.f32 %0, %1, %2;" : "=r"(p1) : "f"(v1.w), "f"(v1.z));
            pk.x = p0; pk.y = p1;
            *(uint2*)(rout + (size_t)slabW*4096 + b1*128 + ((ch1 ^ (b1 & 7)) << 3) + (k1 & 7)) = pk;
        }
        __threadfence();
        BAR_CONSUMERS();
        if (tid == 0) atomicAdd(g_flag + slabW*2 + bhIdx, 1);

        // epilogue pass 2: fp32 out tile (off the recurrence critical path)
        {
            int f0 = tid, f1 = tid + 256;
            int b0 = f0 >> 4, hq0 = f0 & 15;
            int b1 = f1 >> 4, hq1 = f1 & 15;
            float* obase = out + (size_t)t*(BATCH*HID) + hbase;
            *(float4*)&obase[(size_t)(bh + b0)*HID + hq0*4] = v0;
            *(float4*)&obase[(size_t)(bh + b1)*HID + hq1*4] = v1;
        }
    }
}

// ---------------------------------------------------------------------------
extern "C" void kernel_launch(void* const* d_in, const int* in_sizes, int n_in,
                              void* d_out, int out_size) {
    const float *inputs = nullptr, *W_rec = nullptr,
                *b_rec = nullptr,  *W_in  = nullptr;
    for (int i = 0; i < n_in; i++) {
        long n = (long)in_sizes[i];
        if      (n == (long)TSTEPS*BATCH*IN_DIM) inputs = (const float*)d_in[i];
        else if (n == (long)HID*HID)             W_rec  = (const float*)d_in[i];
        else if (n == (long)HID)                 b_rec  = (const float*)d_in[i];
        else if (n == (long)HID*IN_DIM)          W_in   = (const float*)d_in[i];
    }
    float* out = (float*)d_out;

    cudaFuncSetAttribute(rnn_kernel, cudaFuncAttributeMaxDynamicSharedMemorySize, SMEM_TOTAL);

    build_W <<<(450*8192 + 255)/256, 256>>>(W_rec, W_in);
    build_in<<<(TSTEPS*64*IN_DIM + 255)/256, 256>>>(inputs);
    init_k  <<<(2*20*4096 + 255)/256, 256>>>();
    rnn_kernel<<<GRID, 288, SMEM_TOTAL>>>(b_rec, out);
}